// round 6
// baseline (speedup 1.0000x reference)
#include <cuda_runtime.h>
#include <cuda_bf16.h>

#define NN 8192
#define NPAIRS (NN / 2)
#define SLOTS 1024u          // per-pair edge capacity (16MB static total)

// Delta-encoded union-find parent: parent(x) = x + d_pdelta[x]; root iff 0.
// Zero at module load; the union/finish kernel re-zeroes after every run.
__device__ int d_pdelta[NN];
__device__ unsigned int d_ucount;            // strictly-upper positives
__device__ unsigned int d_dcount;            // diagonal positives
__device__ unsigned int d_ecnt[NPAIRS];      // edges found per pair-block
__device__ unsigned int d_edges[NPAIRS * SLOTS];
__device__ unsigned int d_done;              // last-block-done counter

// Lock-free union-find: path halving + CAS hooking toward smaller root.
__device__ __noinline__ void uf_union(int a, int b) {
    while (true) {
        while (true) {                        // find(a)
            int d = d_pdelta[a];
            if (d == 0) break;
            int p = a + d;
            int dp = d_pdelta[p];
            if (dp == 0) { a = p; break; }
            d_pdelta[a] = (p + dp) - a;
            a = p + dp;
        }
        while (true) {                        // find(b)
            int d = d_pdelta[b];
            if (d == 0) break;
            int p = b + d;
            int dp = d_pdelta[p];
            if (dp == 0) { b = p; break; }
            d_pdelta[b] = (p + dp) - b;
            b = p + dp;
        }
        if (a == b) return;
        int lo = min(a, b);
        int hi = max(a, b);
        int old = atomicCAS(&d_pdelta[hi], 0, lo - hi);
        if (old == 0) return;
        a = lo;
        b = hi + old;
    }
}

// Upper-triangle scan, block per row pair (row, NN-1-row): NN+1 elements per
// block. Hot loop: 4 batched LDG.128, straight-line counting, ONE uniform
// warp branch via ballot. Edges are appended to a per-block buffer slice
// (smem counter + STG) — no calls, no divergent latency chains in the scan.
// Exactness: adj is bitwise symmetric -> full positives = 2U + D, and the
// reference's sum//2 = U + D//2 exactly.
__global__ void __launch_bounds__(256) hc_scan(const float* __restrict__ adj) {
    __shared__ unsigned int s_cnt;
    const int t = threadIdx.x;
    const int pair = blockIdx.x;
    const unsigned ebase = (unsigned)pair * SLOTS;
    if (t == 0) s_cnt = 0u;
    __syncthreads();

    unsigned int cnt = 0;

    #pragma unroll
    for (int half = 0; half < 2; half++) {
        const int row = half ? (NN - 1 - pair) : pair;
        const float4* __restrict__ rowp = (const float4*)(adj + (size_t)row * NN);
        const int start4 = row >> 2;           // quad containing the diagonal
        const unsigned enc_row = (unsigned)row << 13;

        if (t == 0) {
            // diagonal quad: cols may be <, ==, or > row
            float4 v = rowp[start4];
            int col0 = start4 << 2;
            float e[4] = {v.x, v.y, v.z, v.w};
            unsigned dd = 0;
            #pragma unroll
            for (int j = 0; j < 4; j++) {
                int col = col0 + j;
                if (e[j] > 0.0f) {
                    if (col == row) dd++;
                    else if (col > row) {
                        cnt++;
                        unsigned base = atomicAdd(&s_cnt, 1u);
                        if (base < SLOTS) d_edges[ebase + base] = enc_row | (unsigned)col;
                        else uf_union(row, col);
                    }
                }
            }
            if (dd) atomicAdd(&d_dcount, dd);
        }

        const int lim = NN / 4;
        // uniform trip count across the block; loads predicated
        for (int ib = start4 + 1; ib < lim; ib += 1024) {
            const float4 NEG = make_float4(-1.f, -1.f, -1.f, -1.f);
            const int i0 = ib + t;
            float4 v0 = NEG, v1 = NEG, v2 = NEG, v3 = NEG;
            if (i0       < lim) v0 = rowp[i0];
            if (i0 + 256 < lim) v1 = rowp[i0 + 256];
            if (i0 + 512 < lim) v2 = rowp[i0 + 512];
            if (i0 + 768 < lim) v3 = rowp[i0 + 768];

            unsigned k0 = (unsigned)(v0.x > 0.f) + (unsigned)(v0.y > 0.f)
                        + (unsigned)(v0.z > 0.f) + (unsigned)(v0.w > 0.f);
            unsigned k1 = (unsigned)(v1.x > 0.f) + (unsigned)(v1.y > 0.f)
                        + (unsigned)(v1.z > 0.f) + (unsigned)(v1.w > 0.f);
            unsigned k2 = (unsigned)(v2.x > 0.f) + (unsigned)(v2.y > 0.f)
                        + (unsigned)(v2.z > 0.f) + (unsigned)(v2.w > 0.f);
            unsigned k3 = (unsigned)(v3.x > 0.f) + (unsigned)(v3.y > 0.f)
                        + (unsigned)(v3.z > 0.f) + (unsigned)(v3.w > 0.f);
            unsigned k = k0 + k1 + k2 + k3;
            cnt += k;

            // uniform warp branch: whole warp skips when no lane has a hit
            if (__ballot_sync(0xFFFFFFFFu, k != 0u)) {
                if (k) {
                    unsigned base = atomicAdd(&s_cnt, k);
                    unsigned idx = base;
                    #pragma unroll
                    for (int q = 0; q < 4; q++) {
                        float4 v = (q == 0) ? v0 : (q == 1) ? v1 : (q == 2) ? v2 : v3;
                        int col0 = (i0 + q * 256) << 2;
                        float e[4] = {v.x, v.y, v.z, v.w};
                        #pragma unroll
                        for (int j = 0; j < 4; j++) {
                            if (e[j] > 0.f) {
                                if (idx < SLOTS)
                                    d_edges[ebase + idx] = enc_row | (unsigned)(col0 + j);
                                else
                                    uf_union(row, col0 + j);
                                idx++;
                            }
                        }
                    }
                }
            }
        }
    }

    // block reduce cnt -> 1 global atomic; publish edge count
    for (int s = 16; s > 0; s >>= 1)
        cnt += __shfl_down_sync(0xFFFFFFFFu, cnt, s);
    __shared__ unsigned int shu[8];
    int lane = t & 31, w = t >> 5;
    if (lane == 0) shu[w] = cnt;
    __syncthreads();
    if (t == 0) {
        unsigned su = 0;
        #pragma unroll
        for (int i = 0; i < 8; i++) su += shu[i];
        atomicAdd(&d_ucount, su);
        d_ecnt[pair] = min(s_cnt, SLOTS);
    }
}

// Union all buffered edges (warp per pair segment), then the last block
// counts roots, computes the loss, and resets all state for the next replay.
__global__ void __launch_bounds__(256) hc_union_finish(float* __restrict__ out) {
    const int t = threadIdx.x;
    const int lane = t & 31;
    const int gwarp = (blockIdx.x * 256 + t) >> 5;
    const int nwarps = (gridDim.x * 256) >> 5;

    for (int p = gwarp; p < NPAIRS; p += nwarps) {
        unsigned n = d_ecnt[p];
        for (unsigned i = lane; i < n; i += 32) {
            unsigned e = d_edges[(unsigned)p * SLOTS + i];
            uf_union((int)(e >> 13), (int)(e & 8191u));
        }
    }

    __syncthreads();
    __threadfence();
    __shared__ unsigned s_last;
    if (t == 0) s_last = atomicAdd(&d_done, 1u);
    __syncthreads();

    if (s_last == gridDim.x - 1) {
        __threadfence();                    // acquire all blocks' union writes
        __shared__ int sh[256];
        const int4* p4 = (const int4*)d_pdelta;
        int roots = 0;
        for (int k = t; k < NN / 4; k += 256) {
            int4 v = p4[k];
            roots += (v.x == 0) + (v.y == 0) + (v.z == 0) + (v.w == 0);
        }
        sh[t] = roots;
        __syncthreads();
        for (int s = 128; s > 0; s >>= 1) {
            if (t < s) sh[t] += sh[t + s];
            __syncthreads();
        }
        if (t == 0) {
            float n_comp  = (float)sh[0];
            unsigned half_edges = d_ucount + (d_dcount >> 1);  // (2U+D)//2
            float n_edges = (float)half_edges;
            float betti1  = n_edges - (float)NN + n_comp;
            float n_cyc   = fmaxf(0.0f, betti1);
            float comp_l  = (n_comp - 1.0f) * (n_comp - 1.0f);
            out[0] = comp_l + n_cyc * n_cyc;
        }
        __syncthreads();
        // reset state for the next replay
        int4* w4 = (int4*)d_pdelta;
        for (int k = t; k < NN / 4; k += 256)
            w4[k] = make_int4(0, 0, 0, 0);
        if (t == 0) { d_ucount = 0u; d_dcount = 0u; d_done = 0u; }
    }
}

extern "C" void kernel_launch(void* const* d_in, const int* in_sizes, int n_in,
                              void* d_out, int out_size) {
    const float* adj = (const float*)d_in[0];
    float* out = (float*)d_out;

    hc_scan<<<NPAIRS, 256>>>(adj);
    hc_union_finish<<<128, 256>>>(out);
}